// round 4
// baseline (speedup 1.0000x reference)
#include <cuda_runtime.h>
#include <cuda_bf16.h>
#include <math.h>

// ---------------------------------------------------------------------------
// WReN forward: loss + accuracy.
// Shapes: B=512, slots=16 (8 ctx + 8 ans), D=512, d=D+9=521, T=2d=1042.
// Padded dims: d -> 544 (K pad), T -> 1056 (K pad), N-grid -> 1152 (9*128).
// All pads are zero-filled so they contribute nothing.
// ---------------------------------------------------------------------------

#define BATCH      512
#define SLOTS      16
#define NROWS_EMB  (BATCH * SLOTS)        // 8192
#define D_EMB      512
#define D_TAG      521
#define KP1        544                    // padded d (layer-1 K)
#define T_DIM      1042
#define KP2        1056                   // padded T (layer-2/3/f K)
#define NP         1152                   // padded N (9 * 128 tiles)
#define NP4        (NP / 4)               // 288 float4 per row
#define NV4        (KP2 / 4)              // 264 valid float4 per row
#define H_ROWS     65536                  // 32768 ctx-pairs + 32768 cc-pairs

// ------------------------- scratch (device globals) ------------------------
__device__ float g_tagged[NROWS_EMB * KP1];     // (8192, 544)  emb + tags
__device__ float g_W1top[KP1 * NP];             // Wg1[:521] padded
__device__ float g_W1bot[KP1 * NP];             // Wg1[521:] padded
__device__ float g_W2p[KP2 * NP];
__device__ float g_W3p[KP2 * NP];
__device__ float g_Wf1p[KP2 * NP];
__device__ float g_bg1p[NP];
__device__ float g_bg2p[NP];
__device__ float g_bg3p[NP];
__device__ float g_bf1p[NP];
__device__ float g_Atop[NROWS_EMB * NP];        // tagged @ W1top
__device__ float g_Bbot[NROWS_EMB * NP];        // tagged @ W1bot
__device__ float g_HA[(size_t)H_ROWS * NP];     // H1 / H3
__device__ float g_HB[(size_t)H_ROWS * NP];     // H2
__device__ float g_ctxsum[BATCH * NP];
__device__ float g_rel[BATCH * 8 * NP];
__device__ float g_H4[BATCH * 8 * NP];
__device__ float g_fout[BATCH * 8];

// ------------------------------- prep kernels ------------------------------
__global__ void pad_weight_kernel(float* __restrict__ dst,
                                  const float* __restrict__ src,
                                  int dstK, int validK, int rowOff) {
    long idx = (long)blockIdx.x * blockDim.x + threadIdx.x;
    long total = (long)dstK * NP;
    if (idx >= total) return;
    int k = (int)(idx / NP);
    int n = (int)(idx % NP);
    float v = 0.f;
    if (k < validK && n < T_DIM)
        v = src[(long)(rowOff + k) * T_DIM + n];
    dst[idx] = v;
}

__global__ void pad_bias_kernel(float* __restrict__ dst,
                                const float* __restrict__ src) {
    int n = blockIdx.x * blockDim.x + threadIdx.x;
    if (n >= NP) return;
    dst[n] = (n < T_DIM) ? src[n] : 0.f;
}

// tags: cols [512..543] of tagged. slot<8 -> eye9[slot], slot>=8 -> eye9[8].
__global__ void tag_kernel(float* __restrict__ tagged) {
    int row = blockIdx.x;          // 0..8191
    int c = threadIdx.x;           // 0..31
    int slot = row & 15;
    int tagidx = (slot < 8) ? slot : 8;
    float v = (c < 9 && c == tagidx) ? 1.f : 0.f;
    tagged[(size_t)row * KP1 + D_EMB + c] = v;
}

// ------------------------------- SGEMM -------------------------------------
// C[M,N] = op(A[M,K] * B[K,N] + bias), 128x128x16 tiles, 8x8 per thread.
// Requires: M%128==0, gridDim.x*128 == padded N, K%16==0, all ld%4==0,
// A/B/C 16B aligned at every float4 access (guaranteed by our layouts).
__global__ void __launch_bounds__(256, 2)
sgemm_kernel(const float* __restrict__ A, int lda,
             const float* __restrict__ B, int ldb,
             float* __restrict__ C, int ldc,
             int K, const float* __restrict__ bias, int doRelu) {
    __shared__ float As[16][132];   // +4 pad: conflict-free transposed stores
    __shared__ float Bs[16][128];

    const int tid = threadIdx.x;
    const int tx  = tid & 15;
    const int ty  = tid >> 4;
    const long bm = (long)blockIdx.y * 128;
    const long bn = (long)blockIdx.x * 128;

    const int aRow = tid >> 2;          // 0..63
    const int aCol = (tid & 3) << 2;    // 0,4,8,12
    const int bRow = tid >> 5;          // 0..7
    const int bCol = (tid & 31) << 2;   // 0..124

    const float* Ab0 = A + (bm + aRow) * (long)lda + aCol;
    const float* Ab1 = Ab0 + 64L * lda;
    const float* Bb0 = B + (long)bRow * ldb + bn + bCol;
    const float* Bb1 = Bb0 + 8L * ldb;

    float4 pa0 = *(const float4*)(Ab0);
    float4 pa1 = *(const float4*)(Ab1);
    float4 pb0 = *(const float4*)(Bb0);
    float4 pb1 = *(const float4*)(Bb1);

    float acc[8][8];
    #pragma unroll
    for (int i = 0; i < 8; i++)
        #pragma unroll
        for (int j = 0; j < 8; j++) acc[i][j] = 0.f;

    for (int k0 = 0; k0 < K; k0 += 16) {
        As[aCol + 0][aRow]      = pa0.x;
        As[aCol + 1][aRow]      = pa0.y;
        As[aCol + 2][aRow]      = pa0.z;
        As[aCol + 3][aRow]      = pa0.w;
        As[aCol + 0][aRow + 64] = pa1.x;
        As[aCol + 1][aRow + 64] = pa1.y;
        As[aCol + 2][aRow + 64] = pa1.z;
        As[aCol + 3][aRow + 64] = pa1.w;
        *(float4*)&Bs[bRow][bCol]     = pb0;
        *(float4*)&Bs[bRow + 8][bCol] = pb1;
        __syncthreads();

        if (k0 + 16 < K) {  // prefetch next tile into registers
            pa0 = *(const float4*)(Ab0 + k0 + 16);
            pa1 = *(const float4*)(Ab1 + k0 + 16);
            pb0 = *(const float4*)(Bb0 + (long)(k0 + 16) * ldb);
            pb1 = *(const float4*)(Bb1 + (long)(k0 + 16) * ldb);
        }

        #pragma unroll
        for (int k = 0; k < 16; k++) {
            float a_frag[8], b_frag[8];
            *(float4*)&a_frag[0] = *(const float4*)&As[k][ty * 4];
            *(float4*)&a_frag[4] = *(const float4*)&As[k][64 + ty * 4];
            *(float4*)&b_frag[0] = *(const float4*)&Bs[k][tx * 4];
            *(float4*)&b_frag[4] = *(const float4*)&Bs[k][64 + tx * 4];
            #pragma unroll
            for (int i = 0; i < 8; i++)
                #pragma unroll
                for (int j = 0; j < 8; j++)
                    acc[i][j] += a_frag[i] * b_frag[j];
        }
        __syncthreads();
    }

    // epilogue
    float bcol[8];
    #pragma unroll
    for (int j = 0; j < 4; j++) {
        bcol[j]     = bias ? bias[bn + tx * 4 + j] : 0.f;
        bcol[j + 4] = bias ? bias[bn + 64 + tx * 4 + j] : 0.f;
    }
    #pragma unroll
    for (int ih = 0; ih < 2; ih++) {
        #pragma unroll
        for (int i = 0; i < 4; i++) {
            long row = bm + ih * 64 + ty * 4 + i;
            float* crow = C + row * (long)ldc + bn;
            #pragma unroll
            for (int jh = 0; jh < 2; jh++) {
                float4 v;
                v.x = acc[ih * 4 + i][jh * 4 + 0] + bcol[jh * 4 + 0];
                v.y = acc[ih * 4 + i][jh * 4 + 1] + bcol[jh * 4 + 1];
                v.z = acc[ih * 4 + i][jh * 4 + 2] + bcol[jh * 4 + 2];
                v.w = acc[ih * 4 + i][jh * 4 + 3] + bcol[jh * 4 + 3];
                if (doRelu) {
                    v.x = fmaxf(v.x, 0.f); v.y = fmaxf(v.y, 0.f);
                    v.z = fmaxf(v.z, 0.f); v.w = fmaxf(v.w, 0.f);
                }
                *(float4*)(crow + jh * 64 + tx * 4) = v;
            }
        }
    }
}

// --------------------- H1 assembly: relu(Atop[j]+Bbot[i]+bg1) ---------------
// rows 0..32767:  ctx pairs (b,i,j) -> Atop[b*16+j] + Bbot[b*16+i]
// rows 32768..65535: cc pairs (b,a,j) -> Atop[b*16+j] + Bbot[b*16+8+a]
__global__ void assemble_h1_kernel(float* __restrict__ H1) {
    int row = blockIdx.x;
    int n4  = threadIdx.x;             // 0..263
    int b, islot, jslot;
    if (row < 32768) {
        b = row >> 6; int rem = row & 63; islot = rem >> 3; jslot = rem & 7;
    } else {
        int r = row - 32768; b = r >> 6; islot = 8 + ((r >> 3) & 7); jslot = r & 7;
    }
    const float4* av = (const float4*)(g_Atop + (size_t)(b * 16 + jslot) * NP);
    const float4* bv = (const float4*)(g_Bbot + (size_t)(b * 16 + islot) * NP);
    const float4* gv = (const float4*)g_bg1p;
    float4 x = av[n4], y = bv[n4], g = gv[n4], o;
    o.x = fmaxf(x.x + y.x + g.x, 0.f);
    o.y = fmaxf(x.y + y.y + g.y, 0.f);
    o.z = fmaxf(x.z + y.z + g.z, 0.f);
    o.w = fmaxf(x.w + y.w + g.w, 0.f);
    ((float4*)(H1 + (size_t)row * NP))[n4] = o;
}

// ctx_sum[b] = sum over 64 ctx-pair rows of H3
__global__ void ctx_sum_kernel(const float* __restrict__ H3) {
    int b = blockIdx.x;                // 0..511
    int n4 = threadIdx.x;              // 0..263
    const float4* base = (const float4*)(H3 + (size_t)b * 64 * NP);
    float4 s = make_float4(0.f, 0.f, 0.f, 0.f);
    #pragma unroll 4
    for (int p = 0; p < 64; p++) {
        float4 v = base[p * NP4 + n4];
        s.x += v.x; s.y += v.y; s.z += v.z; s.w += v.w;
    }
    ((float4*)(g_ctxsum + (size_t)b * NP))[n4] = s;
}

// rel[b*8+a] = ctx_sum[b] + sum_j H3cc[b,a,j]
__global__ void relations_kernel(const float* __restrict__ H3) {
    int r = blockIdx.x;                // 0..4095
    int b = r >> 3, a = r & 7;
    int n4 = threadIdx.x;
    const float4* base =
        (const float4*)(H3 + (size_t)(32768 + b * 64 + a * 8) * NP);
    float4 s = ((const float4*)(g_ctxsum + (size_t)b * NP))[n4];
    #pragma unroll
    for (int j = 0; j < 8; j++) {
        float4 v = base[j * NP4 + n4];
        s.x += v.x; s.y += v.y; s.z += v.z; s.w += v.w;
    }
    ((float4*)(g_rel + (size_t)r * NP))[n4] = s;
}

// f_out[r] = H4[r,:] . Wf2 + bf2  (warp per row)
__global__ void fout_kernel(const float* __restrict__ Wf2,
                            const float* __restrict__ bf2) {
    int r = blockIdx.x * 8 + (threadIdx.x >> 5);
    int lane = threadIdx.x & 31;
    const float* h = g_H4 + (size_t)r * NP;
    float s = 0.f;
    for (int k = lane; k < T_DIM; k += 32) s += h[k] * Wf2[k];
    #pragma unroll
    for (int o = 16; o > 0; o >>= 1) s += __shfl_down_sync(0xffffffffu, s, o);
    if (lane == 0) g_fout[r] = s + bf2[0];
}

// final: BCE loss (mean over 4096) + accuracy (mean over 512)
__global__ void final_kernel(const int* __restrict__ labels,
                             float* __restrict__ out, int out_size) {
    __shared__ float sloss[512];
    __shared__ float sacc[512];
    int b = threadIdx.x;               // 0..511
    int lab = labels[b];
    float lsum = 0.f;
    float best = 0.f;
    int arg = 0;
    #pragma unroll
    for (int a = 0; a < 8; a++) {
        float f = g_fout[b * 8 + a];
        lsum += fmaxf(f, 0.f) - f * (a == lab ? 1.f : 0.f)
                + log1pf(expf(-fabsf(f)));
        if (a == 0 || f > best) { best = f; arg = a; }
    }
    sloss[b] = lsum;
    sacc[b] = (arg == lab) ? 1.f : 0.f;
    __syncthreads();
    for (int stride = 256; stride > 0; stride >>= 1) {
        if (b < stride) {
            sloss[b] += sloss[b + stride];
            sacc[b]  += sacc[b + stride];
        }
        __syncthreads();
    }
    if (b == 0) {
        out[0] = sloss[0] / 4096.f;
        if (out_size >= 2) out[1] = sacc[0] / 512.f;
    }
}

// ------------------------------- host launch --------------------------------
static inline float* sym(const void* s) {
    void* p = nullptr;
    cudaGetSymbolAddress(&p, s);
    return (float*)p;
}

extern "C" void kernel_launch(void* const* d_in, const int* in_sizes, int n_in,
                              void* d_out, int out_size) {
    const float* x      = (const float*)d_in[0];
    const float* W_emb  = (const float*)d_in[1];
    const float* b_emb  = (const float*)d_in[2];
    const float* Wg1    = (const float*)d_in[3];
    const float* bg1    = (const float*)d_in[4];
    const float* Wg2    = (const float*)d_in[5];
    const float* bg2    = (const float*)d_in[6];
    const float* Wg3    = (const float*)d_in[7];
    const float* bg3    = (const float*)d_in[8];
    const float* Wf1    = (const float*)d_in[9];
    const float* bf1    = (const float*)d_in[10];
    const float* Wf2    = (const float*)d_in[11];
    const float* bf2    = (const float*)d_in[12];
    const int*   labels = (const int*)d_in[13];
    float* out = (float*)d_out;

    float* tagged = sym(g_tagged);
    float* w1t = sym(g_W1top);
    float* w1b = sym(g_W1bot);
    float* w2p = sym(g_W2p);
    float* w3p = sym(g_W3p);
    float* wf1p = sym(g_Wf1p);
    float* bg1p = sym(g_bg1p);
    float* bg2p = sym(g_bg2p);
    float* bg3p = sym(g_bg3p);
    float* bf1p = sym(g_bf1p);
    float* atop = sym(g_Atop);
    float* bbot = sym(g_Bbot);
    float* ha = sym(g_HA);
    float* hb = sym(g_HB);
    float* rel = sym(g_rel);
    float* h4 = sym(g_H4);

    // ---- weight/bias padding (cheap, ~25 MB of copies) ----
    {
        long n1 = (long)KP1 * NP;
        long n2 = (long)KP2 * NP;
        int tb = 256;
        pad_weight_kernel<<<(unsigned)((n1 + tb - 1) / tb), tb>>>(w1t, Wg1, KP1, D_TAG, 0);
        pad_weight_kernel<<<(unsigned)((n1 + tb - 1) / tb), tb>>>(w1b, Wg1, KP1, D_TAG, D_TAG);
        pad_weight_kernel<<<(unsigned)((n2 + tb - 1) / tb), tb>>>(w2p, Wg2, KP2, T_DIM, 0);
        pad_weight_kernel<<<(unsigned)((n2 + tb - 1) / tb), tb>>>(w3p, Wg3, KP2, T_DIM, 0);
        pad_weight_kernel<<<(unsigned)((n2 + tb - 1) / tb), tb>>>(wf1p, Wf1, KP2, T_DIM, 0);
        pad_bias_kernel<<<9, 128>>>(bg1p, bg1);
        pad_bias_kernel<<<9, 128>>>(bg2p, bg2);
        pad_bias_kernel<<<9, 128>>>(bg3p, bg3);
        pad_bias_kernel<<<9, 128>>>(bf1p, bf1);
    }

    // ---- embedding: tagged[:, :512] = x(8192,6400) @ W_emb + b_emb ----
    {
        dim3 grid(D_EMB / 128, NROWS_EMB / 128);
        sgemm_kernel<<<grid, 256>>>(x, 6400, W_emb, D_EMB, tagged, KP1,
                                    6400, b_emb, 0);
    }
    tag_kernel<<<NROWS_EMB, 32>>>(tagged);

    // ---- layer-1 factored GEMMs over all 16 slots ----
    {
        dim3 grid(NP / 128, NROWS_EMB / 128);
        sgemm_kernel<<<grid, 256>>>(tagged, KP1, w1t, NP, atop, NP,
                                    KP1, nullptr, 0);
        sgemm_kernel<<<grid, 256>>>(tagged, KP1, w1b, NP, bbot, NP,
                                    KP1, nullptr, 0);
    }

    // ---- H1 = relu(Atop[j] + Bbot[i] + bg1) for all 65536 pairs ----
    assemble_h1_kernel<<<H_ROWS, NV4>>>(ha);

    // ---- layers 2 and 3 ----
    {
        dim3 grid(NP / 128, H_ROWS / 128);
        sgemm_kernel<<<grid, 256>>>(ha, NP, w2p, NP, hb, NP, KP2, bg2p, 1);
        sgemm_kernel<<<grid, 256>>>(hb, NP, w3p, NP, ha, NP, KP2, bg3p, 1);
    }

    // ---- reductions -> relations ----
    ctx_sum_kernel<<<BATCH, NV4>>>(ha);
    relations_kernel<<<BATCH * 8, NV4>>>(ha);

    // ---- f layer ----
    {
        dim3 grid(NP / 128, (BATCH * 8) / 128);
        sgemm_kernel<<<grid, 256>>>(rel, NP, wf1p, NP, h4, NP, KP2, bf1p, 1);
    }
    fout_kernel<<<BATCH, 256>>>(Wf2, bf2);

    // ---- loss + acc ----
    final_kernel<<<1, 512>>>(labels, out, out_size);
}

// round 7
// speedup vs baseline: 3.3677x; 3.3677x over previous
#include <cuda_runtime.h>
#include <cuda_fp16.h>
#include <math.h>
#include <stdint.h>

// ---------------------------------------------------------------------------
// WReN forward, tensor-core GEMMs via fp16 split (f16x3), fp32 accumulate.
// Dual-path GEMM: tcgen05 (arch-specific pass) / mma.sync HMMA (generic pass).
// B=512, slots=16, D=512, d=521, T=1042. KP1=576, N pad 1152, K2 pad 1152.
// ---------------------------------------------------------------------------

#define BATCH      512
#define NROWS_EMB  8192
#define D_EMB      512
#define D_TAG      521
#define KP1        576
#define T_DIM      1042
#define NP         1152
#define K_EMB      6400
#define H_ROWS     65536

// --------------------------- device scratch --------------------------------
__device__ __align__(256) __half g_xh[(size_t)NROWS_EMB * K_EMB];
__device__ __align__(256) __half g_xl[(size_t)NROWS_EMB * K_EMB];
__device__ __align__(256) __half g_Wembt_h[(size_t)D_EMB * K_EMB];
__device__ __align__(256) __half g_Wembt_l[(size_t)D_EMB * K_EMB];
__device__ __align__(256) __half g_W1t_h[NP * KP1];
__device__ __align__(256) __half g_W1t_l[NP * KP1];
__device__ __align__(256) __half g_W1b_h[NP * KP1];
__device__ __align__(256) __half g_W1b_l[NP * KP1];
__device__ __align__(256) __half g_W2t_h[NP * NP];
__device__ __align__(256) __half g_W2t_l[NP * NP];
__device__ __align__(256) __half g_W3t_h[NP * NP];
__device__ __align__(256) __half g_W3t_l[NP * NP];
__device__ __align__(256) __half g_Wf1t_h[NP * NP];
__device__ __align__(256) __half g_Wf1t_l[NP * NP];
__device__ __align__(256) __half g_tagh[(size_t)NROWS_EMB * KP1];
__device__ __align__(256) __half g_tagl[(size_t)NROWS_EMB * KP1];
__device__ __align__(256) float  g_Atop[(size_t)NROWS_EMB * NP];
__device__ __align__(256) float  g_Bbot[(size_t)NROWS_EMB * NP];
__device__ __align__(256) __half g_H1h[(size_t)H_ROWS * NP];
__device__ __align__(256) __half g_H1l[(size_t)H_ROWS * NP];
__device__ __align__(256) __half g_H2h[(size_t)H_ROWS * NP];
__device__ __align__(256) __half g_H2l[(size_t)H_ROWS * NP];
__device__ __align__(256) float  g_H3[(size_t)H_ROWS * NP];
__device__ __align__(256) float  g_ctxsum[BATCH * NP];
__device__ __align__(256) __half g_relh[(size_t)BATCH * 8 * NP];
__device__ __align__(256) __half g_rell[(size_t)BATCH * 8 * NP];
__device__ __align__(256) float  g_H4[(size_t)BATCH * 8 * NP];
__device__ __align__(256) float  g_bg1p[NP];
__device__ __align__(256) float  g_bg2p[NP];
__device__ __align__(256) float  g_bg3p[NP];
__device__ __align__(256) float  g_bf1p[NP];
__device__ __align__(256) float  g_fout[BATCH * 8];

// ------------------------------ PTX helpers --------------------------------
__device__ __forceinline__ uint32_t smem_u32(const void* p) {
    return (uint32_t)__cvta_generic_to_shared(p);
}
__device__ __forceinline__ bool elect_one() {
    uint32_t pred;
    asm volatile("{\n\t.reg .pred p;\n\telect.sync _|p, 0xFFFFFFFF;\n\t"
                 "selp.b32 %0, 1, 0, p;\n\t}" : "=r"(pred));
    return pred != 0;
}
__device__ __forceinline__ uint64_t smem_desc(uint32_t addr) {
    const uint64_t BASE = (2ull << 61) | (1ull << 46) | (64ull << 32) | (1ull << 16);
    return BASE | ((uint64_t)(addr >> 4) & 0x3FFF);
}
__device__ __forceinline__ void mbar_wait(uint32_t addr, int phase) {
    uint32_t done;
    asm volatile("{\n\t.reg .pred p;\n\t"
                 "mbarrier.try_wait.parity.acquire.cta.shared::cta.b64 p, [%1], %2;\n\t"
                 "selp.b32 %0, 1, 0, p;\n\t}"
                 : "=r"(done) : "r"(addr), "r"((uint32_t)phase) : "memory");
    while (!done) {
        asm volatile("{\n\t.reg .pred p;\n\t"
                     "mbarrier.try_wait.parity.acquire.cta.shared::cta.b64 p, [%1], %2, 0x989680;\n\t"
                     "selp.b32 %0, 1, 0, p;\n\t}"
                     : "=r"(done) : "r"(addr), "r"((uint32_t)phase) : "memory");
    }
}
__device__ __forceinline__ void ldsm4(uint32_t addr, uint32_t r[4]) {
    asm volatile("ldmatrix.sync.aligned.m8n8.x4.shared.b16 {%0,%1,%2,%3}, [%4];"
                 : "=r"(r[0]), "=r"(r[1]), "=r"(r[2]), "=r"(r[3]) : "r"(addr));
}
__device__ __forceinline__ void mma16816(float c[4], const uint32_t a[4],
                                         uint32_t b0, uint32_t b1) {
    asm volatile("mma.sync.aligned.m16n8k16.row.col.f32.f16.f16.f32 "
                 "{%0,%1,%2,%3}, {%4,%5,%6,%7}, {%8,%9}, {%0,%1,%2,%3};"
                 : "+f"(c[0]), "+f"(c[1]), "+f"(c[2]), "+f"(c[3])
                 : "r"(a[0]), "r"(a[1]), "r"(a[2]), "r"(a[3]), "r"(b0), "r"(b1));
}

// ------------------------------ GEMM kernel --------------------------------
// C[M,N] = op(A @ W + bias). A: fp16 hi/lo [M,K] K-major. B: fp16 hi/lo [N,K]
// K-major (pre-transposed weights). f16x3: Ah*Bh + Ah*Bl + Al*Bh, fp32 accum.
#define GSTAGE 65536
#define GSMEM_DYN (1024 + 1024 + 3 * GSTAGE)
#define IDESC_F16 ((1u << 4) | (16u << 17) | (8u << 24))

#if defined(__CUDA_ARCH_FEAT_SM103_ALL) || defined(__CUDA_ARCH_SPECIFIC__)
#define TC_LD_X32(r, ta) \
    asm volatile( \
        "tcgen05.ld.sync.aligned.32x32b.x32.b32 " \
        "{%0, %1, %2, %3, %4, %5, %6, %7, " \
        " %8, %9, %10, %11, %12, %13, %14, %15, " \
        " %16, %17, %18, %19, %20, %21, %22, %23, " \
        " %24, %25, %26, %27, %28, %29, %30, %31}, [%32];" \
        : "=r"((r)[0]),  "=r"((r)[1]),  "=r"((r)[2]),  "=r"((r)[3]), \
          "=r"((r)[4]),  "=r"((r)[5]),  "=r"((r)[6]),  "=r"((r)[7]), \
          "=r"((r)[8]),  "=r"((r)[9]),  "=r"((r)[10]), "=r"((r)[11]), \
          "=r"((r)[12]), "=r"((r)[13]), "=r"((r)[14]), "=r"((r)[15]), \
          "=r"((r)[16]), "=r"((r)[17]), "=r"((r)[18]), "=r"((r)[19]), \
          "=r"((r)[20]), "=r"((r)[21]), "=r"((r)[22]), "=r"((r)[23]), \
          "=r"((r)[24]), "=r"((r)[25]), "=r"((r)[26]), "=r"((r)[27]), \
          "=r"((r)[28]), "=r"((r)[29]), "=r"((r)[30]), "=r"((r)[31]) \
        : "r"(ta))

__device__ __forceinline__ void mma_ss_f16(uint32_t d, uint64_t a, uint64_t b,
                                           uint32_t idesc, uint32_t en) {
    asm volatile("{\n\t.reg .pred p;\n\tsetp.ne.u32 p, %4, 0;\n\t"
                 "tcgen05.mma.cta_group::1.kind::f16 [%0], %1, %2, %3, "
                 "{%5, %5, %5, %5}, p;\n\t}"
                 :: "r"(d), "l"(a), "l"(b), "r"(idesc), "r"(en), "r"(0u)
                 : "memory");
}
#endif

__global__ void __launch_bounds__(256, 1)
mma_gemm(const __half* __restrict__ Ah, const __half* __restrict__ Al, int lda,
         const __half* __restrict__ Bh, const __half* __restrict__ Bl, int ldb,
         int K, const float* __restrict__ bias, int doRelu, int outHalf,
         float* __restrict__ Cf, __half* __restrict__ Ch, __half* __restrict__ Cl,
         int ldc) {
    extern __shared__ char dynsmem[];
    const int tid = threadIdx.x;
    const long bm = (long)blockIdx.y * 128;
    const long bn = (long)blockIdx.x * 128;

#if defined(__CUDA_ARCH_FEAT_SM103_ALL) || defined(__CUDA_ARCH_SPECIFIC__)
    // =================== tcgen05 path (arch-specific pass) ===================
    uint32_t base = (smem_u32(dynsmem) + 1023u) & ~1023u;
    uint32_t tiles = base + 1024;

    if (tid < 32) {
        asm volatile("tcgen05.alloc.cta_group::1.sync.aligned.shared::cta.b32 [%0], %1;"
                     :: "r"(base), "r"(512) : "memory");
        asm volatile("tcgen05.relinquish_alloc_permit.cta_group::1.sync.aligned;");
    }
    if (tid == 0) {
        for (int i = 0; i < 3; i++)
            asm volatile("mbarrier.init.shared.b64 [%0], 1;"
                         :: "r"(base + 16 + 8 * i) : "memory");
    }
    __syncthreads();
    uint32_t tmem;
    asm volatile("ld.shared.b32 %0, [%1];" : "=r"(tmem) : "r"(base));

    const int S = K >> 6;
    int ph0 = 0, ph1 = 0, ph2 = 0;

    auto load_stage = [&](int buf, int k0) {
        uint32_t sb = tiles + buf * GSTAGE;
        #pragma unroll
        for (int i = 0; i < 16; i++) {
            int c = tid + i * 256;
            int mat = c >> 10;
            int idx = c & 1023;
            int r = idx >> 3;
            int kk = idx & 7;
            const __half* src;
            if (mat == 0)      src = Ah + (bm + r) * (size_t)lda + k0 + kk * 8;
            else if (mat == 1) src = Al + (bm + r) * (size_t)lda + k0 + kk * 8;
            else if (mat == 2) src = Bh + (bn + r) * (size_t)ldb + k0 + kk * 8;
            else               src = Bl + (bn + r) * (size_t)ldb + k0 + kk * 8;
            uint32_t off = (uint32_t)(r * 128 + kk * 16);
            off = off ^ ((off >> 3) & 0x70);
            uint32_t dst = sb + mat * 16384 + off;
            asm volatile("cp.async.cg.shared.global [%0], [%1], 16;"
                         :: "r"(dst), "l"(src));
        }
        asm volatile("cp.async.commit_group;" ::: "memory");
    };

    load_stage(0, 0);
    load_stage(1, 64);
    asm volatile("cp.async.wait_group 1;" ::: "memory");
    asm volatile("fence.proxy.async.shared::cta;" ::: "memory");
    __syncthreads();

    for (int s = 0; s < S; s++) {
        int cur = s % 3;
        if (tid < 32) {
            if (elect_one()) {
                uint32_t sb = tiles + cur * GSTAGE;
                uint64_t dAh = smem_desc(sb);
                uint64_t dAl = smem_desc(sb + 16384);
                uint64_t dBh = smem_desc(sb + 32768);
                uint64_t dBl = smem_desc(sb + 49152);
                #pragma unroll
                for (int kk = 0; kk < 4; kk++) {
                    uint32_t en0 = (s == 0 && kk == 0) ? 0u : 1u;
                    mma_ss_f16(tmem, dAh + kk * 2, dBh + kk * 2, IDESC_F16, en0);
                    mma_ss_f16(tmem, dAh + kk * 2, dBl + kk * 2, IDESC_F16, 1u);
                    mma_ss_f16(tmem, dAl + kk * 2, dBh + kk * 2, IDESC_F16, 1u);
                }
                asm volatile(
                    "tcgen05.commit.cta_group::1.mbarrier::arrive::one.shared::cluster.b64 [%0];"
                    :: "r"(base + 16 + 8 * cur) : "memory");
            }
        }
        if (s + 2 < S) {
            if (s >= 1) {
                int pb = (s - 1) % 3;
                int ph = (pb == 0) ? ph0 : ((pb == 1) ? ph1 : ph2);
                mbar_wait(base + 16 + 8 * pb, ph);
                if (pb == 0) ph0 ^= 1; else if (pb == 1) ph1 ^= 1; else ph2 ^= 1;
            }
            load_stage((s + 2) % 3, (s + 2) * 64);
            asm volatile("cp.async.wait_group 1;" ::: "memory");
        } else {
            asm volatile("cp.async.wait_group 0;" ::: "memory");
        }
        asm volatile("fence.proxy.async.shared::cta;" ::: "memory");
        __syncthreads();
    }

    {
        int fb = (S - 1) % 3;
        int ph = (fb == 0) ? ph0 : ((fb == 1) ? ph1 : ph2);
        mbar_wait(base + 16 + 8 * fb, ph);
    }
    asm volatile("tcgen05.fence::after_thread_sync;" ::: "memory");

    {
        int w = tid >> 5, lane = tid & 31;
        int subp = w & 3, hsel = w >> 2;
        uint32_t regs[64];
        uint32_t ta = tmem + hsel * 64;
        TC_LD_X32(regs, ta);
        TC_LD_X32(regs + 32, ta + 32);
        asm volatile("tcgen05.wait::ld.sync.aligned;" ::: "memory");
        asm volatile("tcgen05.fence::before_thread_sync;" ::: "memory");

        size_t row = (size_t)(bm + subp * 32 + lane);
        int col0 = (int)bn + hsel * 64;
        if (outHalf) {
            __half2* oh = (__half2*)(Ch + row * (size_t)ldc + col0);
            __half2* ol = (__half2*)(Cl + row * (size_t)ldc + col0);
            #pragma unroll
            for (int j = 0; j < 64; j += 2) {
                float v0 = __uint_as_float(regs[j]);
                float v1 = __uint_as_float(regs[j + 1]);
                if (bias) { v0 += bias[col0 + j]; v1 += bias[col0 + j + 1]; }
                if (doRelu) { v0 = fmaxf(v0, 0.f); v1 = fmaxf(v1, 0.f); }
                __half h0 = __float2half_rn(v0), h1 = __float2half_rn(v1);
                oh[j >> 1] = __halves2half2(h0, h1);
                ol[j >> 1] = __halves2half2(__float2half_rn(v0 - __half2float(h0)),
                                            __float2half_rn(v1 - __half2float(h1)));
            }
        } else {
            float2* of = (float2*)(Cf + row * (size_t)ldc + col0);
            #pragma unroll
            for (int j = 0; j < 64; j += 2) {
                float v0 = __uint_as_float(regs[j]);
                float v1 = __uint_as_float(regs[j + 1]);
                if (bias) { v0 += bias[col0 + j]; v1 += bias[col0 + j + 1]; }
                if (doRelu) { v0 = fmaxf(v0, 0.f); v1 = fmaxf(v1, 0.f); }
                of[j >> 1] = make_float2(v0, v1);
            }
        }
    }
    __syncthreads();
    if (tid < 32) {
        asm volatile("tcgen05.dealloc.cta_group::1.sync.aligned.b32 %0, %1;"
                     :: "r"(tmem), "r"(512));
    }
#else
    // =================== mma.sync HMMA path (generic pass) ===================
    // stage: Ah[128][40h] Al Bh Bl, 80B rows (conflict-free ldmatrix), 2 stages.
    const int lane = tid & 31;
    const int wid = tid >> 5;
    const int wm = (wid & 3) * 32;    // warp rows
    const int wn = (wid >> 2) * 64;   // warp cols
    uint32_t s0 = smem_u32(dynsmem);

    float acc[2][8][4];
    #pragma unroll
    for (int a = 0; a < 2; a++)
        #pragma unroll
        for (int b = 0; b < 8; b++)
            #pragma unroll
            for (int c = 0; c < 4; c++) acc[a][b][c] = 0.f;

    auto load_stage_m = [&](int buf, int k0) {
        uint32_t sb = s0 + buf * 40960;
        #pragma unroll
        for (int i = 0; i < 8; i++) {
            int c = tid + i * 256;      // 0..2047
            int mat = c >> 9;
            int idx = c & 511;
            int r = idx >> 2;
            int ch = idx & 3;
            const __half* src;
            if (mat == 0)      src = Ah + (bm + r) * (size_t)lda + k0 + ch * 8;
            else if (mat == 1) src = Al + (bm + r) * (size_t)lda + k0 + ch * 8;
            else if (mat == 2) src = Bh + (bn + r) * (size_t)ldb + k0 + ch * 8;
            else               src = Bl + (bn + r) * (size_t)ldb + k0 + ch * 8;
            uint32_t dst = sb + mat * 10240 + (uint32_t)(r * 80 + ch * 16);
            asm volatile("cp.async.cg.shared.global [%0], [%1], 16;"
                         :: "r"(dst), "l"(src));
        }
        asm volatile("cp.async.commit_group;" ::: "memory");
    };

    const int g = lane >> 3, li = lane & 7;
    const int aRowAdd = (g & 1) ? 8 : 0, aKAdd = (g & 2) ? 8 : 0;
    const int bRowAdd = (g & 2) ? 8 : 0, bKAdd = (g & 1) ? 8 : 0;

    const int S = K >> 5;
    load_stage_m(0, 0);
    for (int s = 0; s < S; s++) {
        if (s + 1 < S) {
            load_stage_m((s + 1) & 1, (s + 1) * 32);
            asm volatile("cp.async.wait_group 1;" ::: "memory");
        } else {
            asm volatile("cp.async.wait_group 0;" ::: "memory");
        }
        __syncthreads();

        uint32_t sb = s0 + (s & 1) * 40960;
        uint32_t sAh = sb, sAl = sb + 10240, sBh = sb + 20480, sBl = sb + 30720;
        #pragma unroll
        for (int kc = 0; kc < 32; kc += 16) {
            uint32_t ah[2][4], al[2][4], bh[4][4], bl[4][4];
            #pragma unroll
            for (int mi = 0; mi < 2; mi++) {
                uint32_t off = (uint32_t)((wm + mi * 16 + aRowAdd + li) * 80 +
                                          (kc + aKAdd) * 2);
                ldsm4(sAh + off, ah[mi]);
                ldsm4(sAl + off, al[mi]);
            }
            #pragma unroll
            for (int nb = 0; nb < 4; nb++) {
                uint32_t off = (uint32_t)((wn + nb * 16 + bRowAdd + li) * 80 +
                                          (kc + bKAdd) * 2);
                ldsm4(sBh + off, bh[nb]);
                ldsm4(sBl + off, bl[nb]);
            }
            #pragma unroll
            for (int mi = 0; mi < 2; mi++)
                #pragma unroll
                for (int nb = 0; nb < 4; nb++)
                    #pragma unroll
                    for (int nn = 0; nn < 2; nn++) {
                        int n = nb * 2 + nn;
                        mma16816(acc[mi][n], ah[mi], bh[nb][nn * 2], bh[nb][nn * 2 + 1]);
                        mma16816(acc[mi][n], ah[mi], bl[nb][nn * 2], bl[nb][nn * 2 + 1]);
                        mma16816(acc[mi][n], al[mi], bh[nb][nn * 2], bh[nb][nn * 2 + 1]);
                    }
        }
        __syncthreads();
    }

    // epilogue
    auto store2 = [&](size_t row, int col, float v0, float v1) {
        if (bias) { v0 += bias[col]; v1 += bias[col + 1]; }
        if (doRelu) { v0 = fmaxf(v0, 0.f); v1 = fmaxf(v1, 0.f); }
        if (outHalf) {
            __half h0 = __float2half_rn(v0), h1 = __float2half_rn(v1);
            *(__half2*)(Ch + row * (size_t)ldc + col) = __halves2half2(h0, h1);
            *(__half2*)(Cl + row * (size_t)ldc + col) =
                __halves2half2(__float2half_rn(v0 - __half2float(h0)),
                               __float2half_rn(v1 - __half2float(h1)));
        } else {
            *(float2*)(Cf + row * (size_t)ldc + col) = make_float2(v0, v1);
        }
    };
    #pragma unroll
    for (int mi = 0; mi < 2; mi++) {
        size_t row0 = (size_t)(bm + wm + mi * 16 + (lane >> 2));
        #pragma unroll
        for (int n = 0; n < 8; n++) {
            int col = (int)bn + wn + n * 8 + (lane & 3) * 2;
            store2(row0,     col, acc[mi][n][0], acc[mi][n][1]);
            store2(row0 + 8, col, acc[mi][n][2], acc[mi][n][3]);
        }
    }
#endif
}

// ------------------------------ prep kernels -------------------------------
__global__ void xsplit_kernel(const float2* __restrict__ x,
                              __half2* __restrict__ xh,
                              __half2* __restrict__ xl, long n2) {
    long i = (long)blockIdx.x * blockDim.x + threadIdx.x;
    if (i >= n2) return;
    float2 v = x[i];
    __half h0 = __float2half_rn(v.x), h1 = __float2half_rn(v.y);
    xh[i] = __halves2half2(h0, h1);
    xl[i] = __halves2half2(__float2half_rn(v.x - __half2float(h0)),
                           __float2half_rn(v.y - __half2float(h1)));
}

// dst[n*Kw + k] = src[(k+rowOff)*srcLd + n], split to hi/lo, pads zero.
__global__ void wsplit_kernel(__half* __restrict__ dh, __half* __restrict__ dl,
                              const float* __restrict__ src, int Kw,
                              int validK, int validN, int srcLd, int rowOff,
                              long total) {
    long idx = (long)blockIdx.x * blockDim.x + threadIdx.x;
    if (idx >= total) return;
    int n = (int)(idx / Kw);
    int k = (int)(idx % Kw);
    float v = 0.f;
    if (k < validK && n < validN) v = src[(size_t)(k + rowOff) * srcLd + n];
    __half h = __float2half_rn(v);
    dh[idx] = h;
    dl[idx] = __float2half_rn(v - __half2float(h));
}

__global__ void pad_bias_kernel(float* __restrict__ dst,
                                const float* __restrict__ src) {
    int n = blockIdx.x * blockDim.x + threadIdx.x;
    if (n >= NP) return;
    dst[n] = (n < T_DIM) ? src[n] : 0.f;
}

__global__ void tag_kernel() {
    int row = blockIdx.x;          // 0..8191
    int c = threadIdx.x;           // 0..63
    int slot = row & 15;
    int tagidx = (slot < 8) ? slot : 8;
    float v = (c < 9 && c == tagidx) ? 1.f : 0.f;
    g_tagh[(size_t)row * KP1 + D_EMB + c] = __float2half_rn(v);
    g_tagl[(size_t)row * KP1 + D_EMB + c] = __float2half_rn(0.f);
}

__global__ void assemble_h1_kernel() {
    int row = blockIdx.x;
    int n4  = threadIdx.x;             // 0..287
    int b, islot, jslot;
    if (row < 32768) {
        b = row >> 6; int rem = row & 63; islot = rem >> 3; jslot = rem & 7;
    } else {
        int r = row - 32768; b = r >> 6; islot = 8 + ((r >> 3) & 7); jslot = r & 7;
    }
    const float4* av = (const float4*)(g_Atop + (size_t)(b * 16 + jslot) * NP);
    const float4* bv = (const float4*)(g_Bbot + (size_t)(b * 16 + islot) * NP);
    const float4* gv = (const float4*)g_bg1p;
    float4 x = av[n4], y = bv[n4], g = gv[n4];
    float o0 = fmaxf(x.x + y.x + g.x, 0.f);
    float o1 = fmaxf(x.y + y.y + g.y, 0.f);
    float o2 = fmaxf(x.z + y.z + g.z, 0.f);
    float o3 = fmaxf(x.w + y.w + g.w, 0.f);
    __half h0 = __float2half_rn(o0), h1 = __float2half_rn(o1);
    __half h2 = __float2half_rn(o2), h3 = __float2half_rn(o3);
    __half2* oh = (__half2*)(g_H1h + (size_t)row * NP);
    __half2* ol = (__half2*)(g_H1l + (size_t)row * NP);
    oh[2 * n4]     = __halves2half2(h0, h1);
    oh[2 * n4 + 1] = __halves2half2(h2, h3);
    ol[2 * n4]     = __halves2half2(__float2half_rn(o0 - __half2float(h0)),
                                    __float2half_rn(o1 - __half2float(h1)));
    ol[2 * n4 + 1] = __halves2half2(__float2half_rn(o2 - __half2float(h2)),
                                    __float2half_rn(o3 - __half2float(h3)));
}

__global__ void ctx_sum_kernel() {
    int b = blockIdx.x;
    int n4 = threadIdx.x;
    const float4* base = (const float4*)(g_H3 + (size_t)b * 64 * NP);
    float4 s = make_float4(0.f, 0.f, 0.f, 0.f);
    #pragma unroll 4
    for (int p = 0; p < 64; p++) {
        float4 v = base[p * (NP / 4) + n4];
        s.x += v.x; s.y += v.y; s.z += v.z; s.w += v.w;
    }
    ((float4*)(g_ctxsum + (size_t)b * NP))[n4] = s;
}

__global__ void relations_kernel() {
    int r = blockIdx.x;
    int b = r >> 3, a = r & 7;
    int n4 = threadIdx.x;
    const float4* base =
        (const float4*)(g_H3 + (size_t)(32768 + b * 64 + a * 8) * NP);
    float4 s = ((const float4*)(g_ctxsum + (size_t)b * NP))[n4];
    #pragma unroll
    for (int j = 0; j < 8; j++) {
        float4 v = base[j * (NP / 4) + n4];
        s.x += v.x; s.y += v.y; s.z += v.z; s.w += v.w;
    }
    __half h0 = __float2half_rn(s.x), h1 = __float2half_rn(s.y);
    __half h2 = __float2half_rn(s.z), h3 = __float2half_rn(s.w);
    __half2* oh = (__half2*)(g_relh + (size_t)r * NP);
    __half2* ol = (__half2*)(g_rell + (size_t)r * NP);
    oh[2 * n4]     = __halves2half2(h0, h1);
    oh[2 * n4 + 1] = __halves2half2(h2, h3);
    ol[2 * n4]     = __halves2half2(__float2half_rn(s.x - __half2float(h0)),
                                    __float2half_rn(s.y - __half2float(h1)));
    ol[2 * n4 + 1] = __halves2half2(__float2half_rn(s.z - __half2float(h2)),
                                    __float2half_rn(s.w - __half2float(h3)));
}

__global__ void fout_kernel(const float* __restrict__ Wf2,
                            const float* __restrict__ bf2) {
    int r = blockIdx.x * 8 + (threadIdx.x >> 5);
    int lane = threadIdx.x & 31;
    const float* h = g_H4 + (size_t)r * NP;
    float s = 0.f;
    for (int k = lane; k < T_DIM; k += 32) s += h[k] * Wf2[k];
    #pragma unroll
    for (int o = 16; o > 0; o >>= 1) s += __shfl_down_sync(0xffffffffu, s, o);
    if (lane == 0) g_fout[r] = s + bf2[0];
}

__global__ void final_kernel(const int* __restrict__ labels,
                             float* __restrict__ out, int out_size) {
    __shared__ float sloss[512];
    __shared__ float sacc[512];
    int b = threadIdx.x;
    int lab = labels[b];
    float lsum = 0.f, best = 0.f;
    int arg = 0;
    #pragma unroll
    for (int a = 0; a < 8; a++) {
        float f = g_fout[b * 8 + a];
        lsum += fmaxf(f, 0.f) - f * (a == lab ? 1.f : 0.f)
                + log1pf(expf(-fabsf(f)));
        if (a == 0 || f > best) { best = f; arg = a; }
    }
    sloss[b] = lsum;
    sacc[b] = (arg == lab) ? 1.f : 0.f;
    __syncthreads();
    for (int stride = 256; stride > 0; stride >>= 1) {
        if (b < stride) {
            sloss[b] += sloss[b + stride];
            sacc[b]  += sacc[b + stride];
        }
        __syncthreads();
    }
    if (b == 0) {
        out[0] = sloss[0] / 4096.f;
        if (out_size >= 2) out[1] = sacc[0] / 512.f;
    }
}

// ------------------------------- host launch --------------------------------
template <typename T>
static inline T* symp(const void* s) {
    void* p = nullptr;
    cudaGetSymbolAddress(&p, s);
    return (T*)p;
}

extern "C" void kernel_launch(void* const* d_in, const int* in_sizes, int n_in,
                              void* d_out, int out_size) {
    const float* x      = (const float*)d_in[0];
    const float* W_emb  = (const float*)d_in[1];
    const float* b_emb  = (const float*)d_in[2];
    const float* Wg1    = (const float*)d_in[3];
    const float* bg1    = (const float*)d_in[4];
    const float* Wg2    = (const float*)d_in[5];
    const float* bg2    = (const float*)d_in[6];
    const float* Wg3    = (const float*)d_in[7];
    const float* bg3    = (const float*)d_in[8];
    const float* Wf1    = (const float*)d_in[9];
    const float* bf1    = (const float*)d_in[10];
    const float* Wf2    = (const float*)d_in[11];
    const float* bf2    = (const float*)d_in[12];
    const int*   labels = (const int*)d_in[13];
    float* out = (float*)d_out;

    cudaFuncSetAttribute(mma_gemm, cudaFuncAttributeMaxDynamicSharedMemorySize,
                         GSMEM_DYN);

    __half* xh = symp<__half>(g_xh);
    __half* xl = symp<__half>(g_xl);
    __half* weh = symp<__half>(g_Wembt_h);
    __half* wel = symp<__half>(g_Wembt_l);
    __half* w1th = symp<__half>(g_W1t_h);
    __half* w1tl = symp<__half>(g_W1t_l);
    __half* w1bh = symp<__half>(g_W1b_h);
    __half* w1bl = symp<__half>(g_W1b_l);
    __half* w2h = symp<__half>(g_W2t_h);
    __half* w2l = symp<__half>(g_W2t_l);
    __half* w3h = symp<__half>(g_W3t_h);
    __half* w3l = symp<__half>(g_W3t_l);
    __half* wfh = symp<__half>(g_Wf1t_h);
    __half* wfl = symp<__half>(g_Wf1t_l);
    __half* tagh = symp<__half>(g_tagh);
    __half* tagl = symp<__half>(g_tagl);
    float* atop = symp<float>(g_Atop);
    float* bbot = symp<float>(g_Bbot);
    __half* h1h = symp<__half>(g_H1h);
    __half* h1l = symp<__half>(g_H1l);
    __half* h2h = symp<__half>(g_H2h);
    __half* h2l = symp<__half>(g_H2l);
    float* h3 = symp<float>(g_H3);
    __half* relh = symp<__half>(g_relh);
    __half* rell = symp<__half>(g_rell);
    float* h4 = symp<float>(g_H4);
    float* bg1p = symp<float>(g_bg1p);
    float* bg2p = symp<float>(g_bg2p);
    float* bg3p = symp<float>(g_bg3p);
    float* bf1p = symp<float>(g_bf1p);

    // ---- input / weight splitting ----
    {
        long n2 = (long)NROWS_EMB * K_EMB / 2;
        xsplit_kernel<<<(unsigned)((n2 + 255) / 256), 256>>>(
            (const float2*)x, (__half2*)xh, (__half2*)xl, n2);
        long tw = (long)D_EMB * K_EMB;
        wsplit_kernel<<<(unsigned)((tw + 255) / 256), 256>>>(
            weh, wel, W_emb, K_EMB, K_EMB, D_EMB, D_EMB, 0, tw);
        long t1 = (long)NP * KP1;
        wsplit_kernel<<<(unsigned)((t1 + 255) / 256), 256>>>(
            w1th, w1tl, Wg1, KP1, D_TAG, T_DIM, T_DIM, 0, t1);
        wsplit_kernel<<<(unsigned)((t1 + 255) / 256), 256>>>(
            w1bh, w1bl, Wg1, KP1, D_TAG, T_DIM, T_DIM, D_TAG, t1);
        long t2 = (long)NP * NP;
        wsplit_kernel<<<(unsigned)((t2 + 255) / 256), 256>>>(
            w2h, w2l, Wg2, NP, T_DIM, T_DIM, T_DIM, 0, t2);
        wsplit_kernel<<<(unsigned)((t2 + 255) / 256), 256>>>(
            w3h, w3l, Wg3, NP, T_DIM, T_DIM, T_DIM, 0, t2);
        wsplit_kernel<<<(unsigned)((t2 + 255) / 256), 256>>>(
            wfh, wfl, Wf1, NP, T_DIM, T_DIM, T_DIM, 0, t2);
        pad_bias_kernel<<<9, 128>>>(bg1p, bg1);
        pad_bias_kernel<<<9, 128>>>(bg2p, bg2);
        pad_bias_kernel<<<9, 128>>>(bg3p, bg3);
        pad_bias_kernel<<<9, 128>>>(bf1p, bf1);
    }

    // ---- embedding ----
    {
        dim3 grid(D_EMB / 128, NROWS_EMB / 128);
        mma_gemm<<<grid, 256, GSMEM_DYN>>>(xh, xl, K_EMB, weh, wel, K_EMB,
                                           K_EMB, b_emb, 0, 1,
                                           nullptr, tagh, tagl, KP1);
    }
    tag_kernel<<<NROWS_EMB, 64>>>();

    // ---- layer-1 factored GEMMs ----
    {
        dim3 grid(NP / 128, NROWS_EMB / 128);
        mma_gemm<<<grid, 256, GSMEM_DYN>>>(tagh, tagl, KP1, w1th, w1tl, KP1,
                                           KP1, nullptr, 0, 0,
                                           atop, nullptr, nullptr, NP);
        mma_gemm<<<grid, 256, GSMEM_DYN>>>(tagh, tagl, KP1, w1bh, w1bl, KP1,
                                           KP1, nullptr, 0, 0,
                                           bbot, nullptr, nullptr, NP);
    }

    assemble_h1_kernel<<<H_ROWS, NP / 4>>>();

    // ---- layers 2 and 3 ----
    {
        dim3 grid(NP / 128, H_ROWS / 128);
        mma_gemm<<<grid, 256, GSMEM_DYN>>>(h1h, h1l, NP, w2h, w2l, NP,
                                           NP, bg2p, 1, 1,
                                           nullptr, h2h, h2l, NP);
        mma_gemm<<<grid, 256, GSMEM_DYN>>>(h2h, h2l, NP, w3h, w3l, NP,
                                           NP, bg3p, 1, 0,
                                           h3, nullptr, nullptr, NP);
    }

    ctx_sum_kernel<<<BATCH, NP / 4>>>();
    relations_kernel<<<BATCH * 8, NP / 4>>>();

    // ---- f layer ----
    {
        dim3 grid(NP / 128, (BATCH * 8) / 128);
        mma_gemm<<<grid, 256, GSMEM_DYN>>>(relh, rell, NP, wfh, wfl, NP,
                                           NP, bf1p, 1, 0,
                                           h4, nullptr, nullptr, NP);
    }
    fout_kernel<<<BATCH, 256>>>(Wf2, bf2);

    final_kernel<<<1, 512>>>(labels, out, out_size);
}